// round 16
// baseline (speedup 1.0000x reference)
#include <cuda_runtime.h>
#include <cstdint>
#include <cstddef>

// ============================================================================
// conv3x3(512->512, 192x192, pad=1) * mask + bias
// via mma.sync.m16n8k8 TF32 (portable PTX -- tcgen05 unavailable: harness
// compiles through compute_103 PTX, where ptxas rejects tcgen05).
//
// GEMM: D[f, p] = sum_{k=(r,c)} Wt[r][f][c] * X[c][p + off(r)],
//   r = ky*3+kx in [0,9), off(r) = (ky-1)*192 + (kx-1), zero outside image.
// K = 4608 = 144 chunks of 32 (r fixed within a chunk).
//
// CTA: 128 filters x 128 pixels, 256 threads, warp grid 2x4 (warp 64x32).
// Double-buffered SMEM (2 x (A 16KB + B 16KB)), XOR-swizzled 128B rows,
// ldmatrix.x4 fragment loads, global->reg prefetch, one sync per chunk.
// Epilogue: out = mask ? acc + bias : bias.
// ============================================================================

#define H_      192
#define W_      192
#define HW_     36864
#define NCHUNK_ 144

#define STAGE_BYTES 32768
#define SMEM_TOTAL  (2 * STAGE_BYTES)

// Transposed tf32 weights: g_wt[r][f][c] (tf32 bit patterns, rna-rounded).
__device__ __align__(16) uint32_t g_wt[9 * 512 * 512];

// ---------------------------------------------------------------------------
__device__ __forceinline__ uint32_t smem_u32(const void* p) {
    uint32_t a;
    asm("{ .reg .u64 t; cvta.to.shared.u64 t, %1; cvt.u32.u64 %0, t; }"
        : "=r"(a) : "l"(p));
    return a;
}

__device__ __forceinline__ uint32_t f2tf(float f) {
    uint32_t u;
    asm("cvt.rna.tf32.f32 %0, %1;" : "=r"(u) : "f"(f));
    return u;
}

__device__ __forceinline__ void sts128(uint32_t addr, uint32_t a, uint32_t b,
                                       uint32_t c, uint32_t d) {
    asm volatile("st.shared.v4.b32 [%0], {%1,%2,%3,%4};"
                 :: "r"(addr), "r"(a), "r"(b), "r"(c), "r"(d) : "memory");
}

#define LDSM4(r0, r1, r2, r3, addr) \
    asm volatile("ldmatrix.sync.aligned.m8n8.x4.shared.b16 {%0,%1,%2,%3}, [%4];" \
                 : "=r"(r0), "=r"(r1), "=r"(r2), "=r"(r3) : "r"(addr))

#define MMA_TF32(c, a, b0v, b1v) \
    asm volatile("mma.sync.aligned.m16n8k8.row.col.f32.tf32.tf32.f32 " \
                 "{%0,%1,%2,%3}, {%4,%5,%6,%7}, {%8,%9}, {%0,%1,%2,%3};" \
                 : "+f"((c)[0]), "+f"((c)[1]), "+f"((c)[2]), "+f"((c)[3]) \
                 : "r"((a)[0]), "r"((a)[1]), "r"((a)[2]), "r"((a)[3]), \
                   "r"(b0v), "r"(b1v))

// ---------------------------------------------------------------------------
// prep: w[f][c][3][3] (f32) -> g_wt[r][f][c] (tf32 bits, rna-rounded)
// ---------------------------------------------------------------------------
__global__ void prep_wt(const float* __restrict__ w) {
    const int t = blockIdx.x * 256 + threadIdx.x;        // f*512 + c
    const int f = t >> 9;
    const int c = t & 511;
    const float* src = w + (size_t)t * 9;                // f*4608 + c*9
#pragma unroll
    for (int r = 0; r < 9; r++) {
        g_wt[((size_t)(r * 512 + f) << 9) + c] = f2tf(src[r]);
    }
}

// ---------------------------------------------------------------------------
// main kernel
// ---------------------------------------------------------------------------
__global__ __launch_bounds__(256, 1)
void conv_main(const float* __restrict__ x,
               const float* __restrict__ bias,
               const int*   __restrict__ mask,
               float*       __restrict__ out) {
    extern __shared__ char smem[];
    const uint32_t sb = smem_u32(smem);

    const int tid  = threadIdx.x;
    const int lane = tid & 31;
    const int wid  = tid >> 5;
    const int wm   = wid >> 2;      // 0..1  (64-filter rows)
    const int wn   = wid & 3;       // 0..3  (32-pixel cols)

    const int pBase = blockIdx.x * 128;
    const int fBase = blockIdx.y * 128;

    // ---- staging thread mapping ----
    const int cbA = tid & 7;        // A: 16B k-chunk (kq)
    const int fiA = tid >> 3;       // A: filter row 0..31 (+32*i)
    const int nB  = tid & 127;      // B: pixel row within tile
    const int hB  = tid >> 7;       // B: k-half (kq = hB*4 + q)
    const int p   = pBase + nB;
    const int y   = p / W_;
    const int xc  = p % W_;

    // ---- per-lane ldmatrix offsets ----
    const int l7   = lane & 7;
    const int aRow = l7 + ((lane >> 3) & 1) * 8;   // A x4: tiles (m0-7,q0),(m8-15,q0),(m0-7,q1),(m8-15,q1)
    const int aQ   = lane >> 4;
    const int bRow = l7 + ((lane >> 4) & 1) * 8;   // B x4: (n0-7,q0),(n0-7,q1),(n8-15,q0),(n8-15,q1)
    const int bQ   = (lane >> 3) & 1;

    float acc[4][4][4];
#pragma unroll
    for (int i = 0; i < 4; i++)
#pragma unroll
        for (int j = 0; j < 4; j++)
#pragma unroll
            for (int q = 0; q < 4; q++) acc[i][j][q] = 0.0f;

    float4 aS[4];
    float  bS[4][4];

    // -------- LDG helpers (chunk kc) --------
    auto ldg_chunk = [&](int kc) {
        const int r  = kc >> 4;
        const int c0 = (kc & 15) << 5;
        // A: g_wt[r][fBase+fiA+32i][c0 + cbA*4 .. +3]
        const float4* wt4 = (const float4*)g_wt +
            ((((size_t)(r * 512 + fBase + fiA)) << 9) + c0) / 4 + cbA;
#pragma unroll
        for (int i = 0; i < 4; i++)
            aS[i] = wt4[(size_t)i * 32 * 128];   // +32 filters = 32*512 floats = 32*128 float4
        // B: x[c0 + hB*16 + q*4 + j][p + off]
        const int dy = r / 3 - 1;
        const int dx = r % 3 - 1;
        const bool ok = ((unsigned)(y + dy) < (unsigned)H_) &&
                        ((unsigned)(xc + dx) < (unsigned)W_);
        const float* xb = x + (size_t)(c0 + hB * 16) * HW_ + (p + dy * W_ + dx);
#pragma unroll
        for (int q = 0; q < 4; q++) {
            if (ok) {
                const float* pc = xb + (size_t)(q * 4) * HW_;
                bS[q][0] = pc[0];
                bS[q][1] = pc[HW_];
                bS[q][2] = pc[2 * HW_];
                bS[q][3] = pc[3 * HW_];
            } else {
                bS[q][0] = bS[q][1] = bS[q][2] = bS[q][3] = 0.0f;
            }
        }
    };

    // -------- STS into stage s (A already tf32; B needs cvt) --------
    auto sts_chunk = [&](int s) {
        const uint32_t As = sb + (uint32_t)s * STAGE_BYTES;
        const uint32_t Bs = As + 16384u;
        const uint32_t aswz = (uint32_t)((cbA ^ (fiA & 7)) << 4);
#pragma unroll
        for (int i = 0; i < 4; i++) {
            sts128(As + (uint32_t)((fiA + 32 * i) * 128) + aswz,
                   __float_as_uint(aS[i].x), __float_as_uint(aS[i].y),
                   __float_as_uint(aS[i].z), __float_as_uint(aS[i].w));
        }
#pragma unroll
        for (int q = 0; q < 4; q++) {
            const int kq = hB * 4 + q;
            sts128(Bs + (uint32_t)(nB * 128) + (uint32_t)((kq ^ (nB & 7)) << 4),
                   f2tf(bS[q][0]), f2tf(bS[q][1]),
                   f2tf(bS[q][2]), f2tf(bS[q][3]));
        }
    };

    // -------- prologue --------
    ldg_chunk(0);
    sts_chunk(0);
    __syncthreads();

    // -------- main loop --------
    for (int kc = 0; kc < NCHUNK_; kc++) {
        const int s = kc & 1;
        if (kc + 1 < NCHUNK_) ldg_chunk(kc + 1);

        const uint32_t As = sb + (uint32_t)s * STAGE_BYTES;
        const uint32_t Bs = As + 16384u;

#pragma unroll
        for (int ks = 0; ks < 4; ks++) {
            uint32_t aF[4][4];
#pragma unroll
            for (int mt = 0; mt < 4; mt++) {
                const int m = wm * 64 + mt * 16 + aRow;
                const uint32_t addr = As + (uint32_t)(m * 128) +
                                      (uint32_t)((((2 * ks + aQ) ^ l7)) << 4);
                LDSM4(aF[mt][0], aF[mt][1], aF[mt][2], aF[mt][3], addr);
            }
            uint32_t bF[2][4];
#pragma unroll
            for (int np = 0; np < 2; np++) {
                const int n = wn * 32 + np * 16 + bRow;
                const uint32_t addr = Bs + (uint32_t)(n * 128) +
                                      (uint32_t)((((2 * ks + bQ) ^ l7)) << 4);
                LDSM4(bF[np][0], bF[np][1], bF[np][2], bF[np][3], addr);
            }
#pragma unroll
            for (int mt = 0; mt < 4; mt++) {
#pragma unroll
                for (int nt = 0; nt < 4; nt++) {
                    MMA_TF32(acc[mt][nt], aF[mt],
                             bF[nt >> 1][(nt & 1) * 2],
                             bF[nt >> 1][(nt & 1) * 2 + 1]);
                }
            }
        }

        if (kc + 1 < NCHUNK_) sts_chunk(s ^ 1);
        __syncthreads();
    }

    // -------- epilogue: out = mask ? acc + bias : bias --------
#pragma unroll
    for (int mt = 0; mt < 4; mt++) {
        const int f = fBase + wm * 64 + mt * 16 + (lane >> 2);
        const float bv0 = bias[f];
        const float bv8 = bias[f + 8];
        float* orow = out + (size_t)f * HW_;
#pragma unroll
        for (int nt = 0; nt < 4; nt++) {
            const int pix = pBase + wn * 32 + nt * 8 + 2 * (lane & 3);
            const float m0 = (float)mask[pix];
            const float m1 = (float)mask[pix + 1];
            float2 v0, v1;
            v0.x = fmaf(m0, acc[mt][nt][0], bv0);
            v0.y = fmaf(m1, acc[mt][nt][1], bv0);
            v1.x = fmaf(m0, acc[mt][nt][2], bv8);
            v1.y = fmaf(m1, acc[mt][nt][3], bv8);
            *(float2*)(orow + pix) = v0;
            *(float2*)(orow + (size_t)8 * HW_ + pix) = v1;
        }
    }
}

// ---------------------------------------------------------------------------
// launch
// ---------------------------------------------------------------------------
extern "C" void kernel_launch(void* const* d_in, const int* in_sizes, int n_in,
                              void* d_out, int out_size) {
    const float* x = nullptr;
    const float* w = nullptr;
    const float* b = nullptr;
    const int* mask = nullptr;
    for (int i = 0; i < n_in; i++) {
        switch (in_sizes[i]) {
            case 18874368: x    = (const float*)d_in[i]; break;  // 512*192*192
            case 2359296:  w    = (const float*)d_in[i]; break;  // 512*512*3*3
            case 512:      b    = (const float*)d_in[i]; break;
            case 36864:    mask = (const int*)d_in[i];   break;  // 192*192
            default: break;
        }
    }
    float* out = (float*)d_out;

    prep_wt<<<1024, 256>>>(w);

    cudaFuncSetAttribute(conv_main, cudaFuncAttributeMaxDynamicSharedMemorySize,
                         SMEM_TOTAL);
    dim3 grid(HW_ / 128, 4);   // (288, 4)
    conv_main<<<grid, 256, SMEM_TOTAL>>>(x, b, mask, out);
}

// round 17
// speedup vs baseline: 1.0005x; 1.0005x over previous
#include <cuda_runtime.h>
#include <cstdint>
#include <cstddef>

// ============================================================================
// conv3x3(512->512, 192x192, pad=1) * mask + bias
// via mma.sync.m16n8k8 TF32 (portable PTX -- tcgen05 unavailable: harness
// compiles through compute_103 PTX, where ptxas rejects tcgen05).
//
// GEMM: D[f, p] = sum_{k=(r,c)} Wt[r][f][c] * X[c][p + off(r)],
//   r = ky*3+kx in [0,9), off(r) = (ky-1)*192 + (kx-1), zero outside image.
// K = 4608 = 144 chunks of 32 (r fixed within a chunk).
//
// CTA: 128 filters x 128 pixels, 256 threads, warp grid 2x4 (warp 64x32).
// Double-buffered SMEM (2 x (A 16KB + B 16KB)), XOR-swizzled 128B rows,
// ldmatrix.x4 fragment loads, global->reg prefetch, one sync per chunk.
// Epilogue: out = mask ? acc + bias : bias.
// ============================================================================

#define H_      192
#define W_      192
#define HW_     36864
#define NCHUNK_ 144

#define STAGE_BYTES 32768
#define SMEM_TOTAL  (2 * STAGE_BYTES)

// Transposed tf32 weights: g_wt[r][f][c] (tf32 bit patterns, rna-rounded).
__device__ __align__(16) uint32_t g_wt[9 * 512 * 512];

// ---------------------------------------------------------------------------
__device__ __forceinline__ uint32_t smem_u32(const void* p) {
    uint32_t a;
    asm("{ .reg .u64 t; cvta.to.shared.u64 t, %1; cvt.u32.u64 %0, t; }"
        : "=r"(a) : "l"(p));
    return a;
}

__device__ __forceinline__ uint32_t f2tf(float f) {
    uint32_t u;
    asm("cvt.rna.tf32.f32 %0, %1;" : "=r"(u) : "f"(f));
    return u;
}

__device__ __forceinline__ void sts128(uint32_t addr, uint32_t a, uint32_t b,
                                       uint32_t c, uint32_t d) {
    asm volatile("st.shared.v4.b32 [%0], {%1,%2,%3,%4};"
                 :: "r"(addr), "r"(a), "r"(b), "r"(c), "r"(d) : "memory");
}

#define LDSM4(r0, r1, r2, r3, addr) \
    asm volatile("ldmatrix.sync.aligned.m8n8.x4.shared.b16 {%0,%1,%2,%3}, [%4];" \
                 : "=r"(r0), "=r"(r1), "=r"(r2), "=r"(r3) : "r"(addr))

#define MMA_TF32(c, a, b0v, b1v) \
    asm volatile("mma.sync.aligned.m16n8k8.row.col.f32.tf32.tf32.f32 " \
                 "{%0,%1,%2,%3}, {%4,%5,%6,%7}, {%8,%9}, {%0,%1,%2,%3};" \
                 : "+f"((c)[0]), "+f"((c)[1]), "+f"((c)[2]), "+f"((c)[3]) \
                 : "r"((a)[0]), "r"((a)[1]), "r"((a)[2]), "r"((a)[3]), \
                   "r"(b0v), "r"(b1v))

// ---------------------------------------------------------------------------
// prep: w[f][c][3][3] (f32) -> g_wt[r][f][c] (tf32 bits, rna-rounded)
// ---------------------------------------------------------------------------
__global__ void prep_wt(const float* __restrict__ w) {
    const int t = blockIdx.x * 256 + threadIdx.x;        // f*512 + c
    const int f = t >> 9;
    const int c = t & 511;
    const float* src = w + (size_t)t * 9;                // f*4608 + c*9
#pragma unroll
    for (int r = 0; r < 9; r++) {
        g_wt[((size_t)(r * 512 + f) << 9) + c] = f2tf(src[r]);
    }
}

// ---------------------------------------------------------------------------
// main kernel
// ---------------------------------------------------------------------------
__global__ __launch_bounds__(256, 1)
void conv_main(const float* __restrict__ x,
               const float* __restrict__ bias,
               const int*   __restrict__ mask,
               float*       __restrict__ out) {
    extern __shared__ char smem[];
    const uint32_t sb = smem_u32(smem);

    const int tid  = threadIdx.x;
    const int lane = tid & 31;
    const int wid  = tid >> 5;
    const int wm   = wid >> 2;      // 0..1  (64-filter rows)
    const int wn   = wid & 3;       // 0..3  (32-pixel cols)

    const int pBase = blockIdx.x * 128;
    const int fBase = blockIdx.y * 128;

    // ---- staging thread mapping ----
    const int cbA = tid & 7;        // A: 16B k-chunk (kq)
    const int fiA = tid >> 3;       // A: filter row 0..31 (+32*i)
    const int nB  = tid & 127;      // B: pixel row within tile
    const int hB  = tid >> 7;       // B: k-half (kq = hB*4 + q)
    const int p   = pBase + nB;
    const int y   = p / W_;
    const int xc  = p % W_;

    // ---- per-lane ldmatrix offsets ----
    const int l7   = lane & 7;
    const int aRow = l7 + ((lane >> 3) & 1) * 8;   // A x4: tiles (m0-7,q0),(m8-15,q0),(m0-7,q1),(m8-15,q1)
    const int aQ   = lane >> 4;
    const int bRow = l7 + ((lane >> 4) & 1) * 8;   // B x4: (n0-7,q0),(n0-7,q1),(n8-15,q0),(n8-15,q1)
    const int bQ   = (lane >> 3) & 1;

    float acc[4][4][4];
#pragma unroll
    for (int i = 0; i < 4; i++)
#pragma unroll
        for (int j = 0; j < 4; j++)
#pragma unroll
            for (int q = 0; q < 4; q++) acc[i][j][q] = 0.0f;

    float4 aS[4];
    float  bS[4][4];

    // -------- LDG helpers (chunk kc) --------
    auto ldg_chunk = [&](int kc) {
        const int r  = kc >> 4;
        const int c0 = (kc & 15) << 5;
        // A: g_wt[r][fBase+fiA+32i][c0 + cbA*4 .. +3]
        const float4* wt4 = (const float4*)g_wt +
            ((((size_t)(r * 512 + fBase + fiA)) << 9) + c0) / 4 + cbA;
#pragma unroll
        for (int i = 0; i < 4; i++)
            aS[i] = wt4[(size_t)i * 32 * 128];   // +32 filters = 32*512 floats = 32*128 float4
        // B: x[c0 + hB*16 + q*4 + j][p + off]
        const int dy = r / 3 - 1;
        const int dx = r % 3 - 1;
        const bool ok = ((unsigned)(y + dy) < (unsigned)H_) &&
                        ((unsigned)(xc + dx) < (unsigned)W_);
        const float* xb = x + (size_t)(c0 + hB * 16) * HW_ + (p + dy * W_ + dx);
#pragma unroll
        for (int q = 0; q < 4; q++) {
            if (ok) {
                const float* pc = xb + (size_t)(q * 4) * HW_;
                bS[q][0] = pc[0];
                bS[q][1] = pc[HW_];
                bS[q][2] = pc[2 * HW_];
                bS[q][3] = pc[3 * HW_];
            } else {
                bS[q][0] = bS[q][1] = bS[q][2] = bS[q][3] = 0.0f;
            }
        }
    };

    // -------- STS into stage s (A already tf32; B needs cvt) --------
    auto sts_chunk = [&](int s) {
        const uint32_t As = sb + (uint32_t)s * STAGE_BYTES;
        const uint32_t Bs = As + 16384u;
        const uint32_t aswz = (uint32_t)((cbA ^ (fiA & 7)) << 4);
#pragma unroll
        for (int i = 0; i < 4; i++) {
            sts128(As + (uint32_t)((fiA + 32 * i) * 128) + aswz,
                   __float_as_uint(aS[i].x), __float_as_uint(aS[i].y),
                   __float_as_uint(aS[i].z), __float_as_uint(aS[i].w));
        }
#pragma unroll
        for (int q = 0; q < 4; q++) {
            const int kq = hB * 4 + q;
            sts128(Bs + (uint32_t)(nB * 128) + (uint32_t)((kq ^ (nB & 7)) << 4),
                   f2tf(bS[q][0]), f2tf(bS[q][1]),
                   f2tf(bS[q][2]), f2tf(bS[q][3]));
        }
    };

    // -------- prologue --------
    ldg_chunk(0);
    sts_chunk(0);
    __syncthreads();

    // -------- main loop --------
    for (int kc = 0; kc < NCHUNK_; kc++) {
        const int s = kc & 1;
        if (kc + 1 < NCHUNK_) ldg_chunk(kc + 1);

        const uint32_t As = sb + (uint32_t)s * STAGE_BYTES;
        const uint32_t Bs = As + 16384u;

#pragma unroll
        for (int ks = 0; ks < 4; ks++) {
            uint32_t aF[4][4];
#pragma unroll
            for (int mt = 0; mt < 4; mt++) {
                const int m = wm * 64 + mt * 16 + aRow;
                const uint32_t addr = As + (uint32_t)(m * 128) +
                                      (uint32_t)((((2 * ks + aQ) ^ l7)) << 4);
                LDSM4(aF[mt][0], aF[mt][1], aF[mt][2], aF[mt][3], addr);
            }
            uint32_t bF[2][4];
#pragma unroll
            for (int np = 0; np < 2; np++) {
                const int n = wn * 32 + np * 16 + bRow;
                const uint32_t addr = Bs + (uint32_t)(n * 128) +
                                      (uint32_t)((((2 * ks + bQ) ^ l7)) << 4);
                LDSM4(bF[np][0], bF[np][1], bF[np][2], bF[np][3], addr);
            }
#pragma unroll
            for (int mt = 0; mt < 4; mt++) {
#pragma unroll
                for (int nt = 0; nt < 4; nt++) {
                    MMA_TF32(acc[mt][nt], aF[mt],
                             bF[nt >> 1][(nt & 1) * 2],
                             bF[nt >> 1][(nt & 1) * 2 + 1]);
                }
            }
        }

        if (kc + 1 < NCHUNK_) sts_chunk(s ^ 1);
        __syncthreads();
    }

    // -------- epilogue: out = mask ? acc + bias : bias --------
#pragma unroll
    for (int mt = 0; mt < 4; mt++) {
        const int f = fBase + wm * 64 + mt * 16 + (lane >> 2);
        const float bv0 = bias[f];
        const float bv8 = bias[f + 8];
        float* orow = out + (size_t)f * HW_;
#pragma unroll
        for (int nt = 0; nt < 4; nt++) {
            const int pix = pBase + wn * 32 + nt * 8 + 2 * (lane & 3);
            const float m0 = (float)mask[pix];
            const float m1 = (float)mask[pix + 1];
            float2 v0, v1;
            v0.x = fmaf(m0, acc[mt][nt][0], bv0);
            v0.y = fmaf(m1, acc[mt][nt][1], bv0);
            v1.x = fmaf(m0, acc[mt][nt][2], bv8);
            v1.y = fmaf(m1, acc[mt][nt][3], bv8);
            *(float2*)(orow + pix) = v0;
            *(float2*)(orow + (size_t)8 * HW_ + pix) = v1;
        }
    }
}

// ---------------------------------------------------------------------------
// launch
// ---------------------------------------------------------------------------
extern "C" void kernel_launch(void* const* d_in, const int* in_sizes, int n_in,
                              void* d_out, int out_size) {
    const float* x = nullptr;
    const float* w = nullptr;
    const float* b = nullptr;
    const int* mask = nullptr;
    for (int i = 0; i < n_in; i++) {
        switch (in_sizes[i]) {
            case 18874368: x    = (const float*)d_in[i]; break;  // 512*192*192
            case 2359296:  w    = (const float*)d_in[i]; break;  // 512*512*3*3
            case 512:      b    = (const float*)d_in[i]; break;
            case 36864:    mask = (const int*)d_in[i];   break;  // 192*192
            default: break;
        }
    }
    float* out = (float*)d_out;

    prep_wt<<<1024, 256>>>(w);

    cudaFuncSetAttribute(conv_main, cudaFuncAttributeMaxDynamicSharedMemorySize,
                         SMEM_TOTAL);
    dim3 grid(HW_ / 128, 4);   // (288, 4)
    conv_main<<<grid, 256, SMEM_TOTAL>>>(x, b, mask, out);
}